// round 15
// baseline (speedup 1.0000x reference)
#include <cuda_runtime.h>
#include <cuda_bf16.h>
#include <math_constants.h>
#include <cstdint>

// Cross-entropy: mean over rows of (logsumexp(row) - row[target]).
// B=8192 rows, V=50257 cols, fp32 logits, int32 targets.
// SINGLE launch: grid 8193. CTAs [0,8192) stream one row each (one-pass
// online logsumexp, float4 __ldcs, misalignment prologue; ~88% DRAM).
// CTA 8192 (scheduled last) spins until all rows are done, then reduces the
// 32KB loss array via two 16KB cp.async.bulk pulls into smem + LDS tree.
// This removes the ~4.5us fixed cost of a second kernel launch.

#define B_ROWS   8192
#define V_COLS   50257
#define THREADS  256
#define L2E      1.4426950408889634f   // log2(e)
#define INV_L2E  0.6931471805599453f   // ln(2)

#define CHUNK_FLOATS 4096              // 16KB per bulk-copy chunk
#define CHUNK_BYTES  (CHUNK_FLOATS * 4)

__device__ __align__(16) float g_row_loss[B_ROWS];
__device__ unsigned int g_done;        // zero-init; reset by spinner each launch

__device__ __forceinline__ float ex2f(float x) {
    float y;
    asm("ex2.approx.ftz.f32 %0, %1;" : "=f"(y) : "f"(x));
    return y;
}

// Online update of (m, s): s = sum_i 2^((x_i - m) * L2E). One MUFU/element.
__device__ __forceinline__ void online_update(float x, float& m, float& s) {
    float d = x - m;
    float e = ex2f(-fabsf(d) * L2E);
    if (d > 0.0f) {
        s = fmaf(s, e, 1.0f);
        m = x;
    } else {
        s += e;
    }
}

__device__ __forceinline__ void online_merge(float mo, float so, float& m, float& s) {
    float M = fmaxf(m, mo);
    s = s * ex2f((m - M) * L2E) + so * ex2f((mo - M) * L2E);
    m = M;
}

__global__ __launch_bounds__(THREADS, 8)
void ce_fused_kernel(const float* __restrict__ inp,
                     const int* __restrict__ tgt,
                     float* __restrict__ out) {
    __shared__ __align__(16) float buf[CHUNK_FLOATS];   // 16KB (spinner only)
    __shared__ __align__(8) unsigned long long mbar;
    __shared__ float sh_a[THREADS / 32];
    __shared__ float sh_b[THREADS / 32];

    const int wid = threadIdx.x >> 5;
    const int lid = threadIdx.x & 31;

    if (blockIdx.x < B_ROWS) {
        // ---------------- Row worker (proven hot path) ----------------
        const int row = blockIdx.x;
        const float* rowp = inp + (long long)row * V_COLS;

        // Alignment split (row stride 50257*4B is only 4B-aligned).
        const int mis  = (int)((((uintptr_t)rowp) >> 2) & 3);
        const int pre  = (4 - mis) & 3;
        const int nvec = (V_COLS - pre) >> 2;
        const int tail = V_COLS - pre - (nvec << 2);
        const float4* p4 = reinterpret_cast<const float4*>(rowp + pre);

        float m = -CUDART_INF_F;
        float s = 0.0f;

        if (threadIdx.x < pre) {
            online_update(__ldcs(rowp + threadIdx.x), m, s);
        }

        #pragma unroll 4
        for (int i = threadIdx.x; i < nvec; i += THREADS) {
            float4 v = __ldcs(p4 + i);
            online_update(v.x, m, s);
            online_update(v.y, m, s);
            online_update(v.z, m, s);
            online_update(v.w, m, s);
        }

        if (threadIdx.x < tail) {
            online_update(__ldcs(rowp + pre + (nvec << 2) + threadIdx.x), m, s);
        }

        #pragma unroll
        for (int off = 16; off > 0; off >>= 1) {
            float mo = __shfl_xor_sync(0xffffffffu, m, off);
            float so = __shfl_xor_sync(0xffffffffu, s, off);
            online_merge(mo, so, m, s);
        }

        if (lid == 0) { sh_a[wid] = m; sh_b[wid] = s; }
        __syncthreads();

        if (threadIdx.x == 0) {
            m = sh_a[0]; s = sh_b[0];
            #pragma unroll
            for (int w = 1; w < THREADS / 32; ++w) {
                online_merge(sh_a[w], sh_b[w], m, s);
            }
            float lse = fmaf(__log2f(s), INV_L2E, m);   // m + ln(s)
            int t = tgt[row];
            t = min(max(t, 0), V_COLS - 1);
            float picked = __ldg(rowp + t);
            g_row_loss[row] = lse - picked;
            __threadfence();
            atomicAdd(&g_done, 1u);
        }
        return;
    }

    // ---------------- Spinner CTA (blockIdx.x == B_ROWS) ----------------
    const uint32_t mbar_addr = (uint32_t)__cvta_generic_to_shared(&mbar);
    const uint32_t buf_addr  = (uint32_t)__cvta_generic_to_shared(buf);

    if (threadIdx.x == 0) {
        // Wait for all 8192 row CTAs.
        unsigned int v;
        do {
            asm volatile("ld.acquire.gpu.u32 %0, [%1];"
                         : "=r"(v) : "l"(&g_done) : "memory");
            if (v != (unsigned int)B_ROWS) __nanosleep(128);
        } while (v != (unsigned int)B_ROWS);
        g_done = 0;   // reset for next graph replay (all adders finished)
        asm volatile("mbarrier.init.shared.b64 [%0], 1;" :: "r"(mbar_addr) : "memory");
        asm volatile("fence.proxy.async;" ::: "memory");
    }
    __syncthreads();

    float acc = 0.0f;
    #pragma unroll
    for (int c = 0; c < 2; ++c) {
        if (threadIdx.x == 0) {
            asm volatile("mbarrier.arrive.expect_tx.shared.b64 _, [%0], %1;"
                         :: "r"(mbar_addr), "r"((uint32_t)CHUNK_BYTES) : "memory");
            asm volatile(
                "cp.async.bulk.shared::cta.global.mbarrier::complete_tx::bytes [%0], [%1], %2, [%3];"
                :: "r"(buf_addr), "l"(g_row_loss + c * CHUNK_FLOATS),
                   "r"((uint32_t)CHUNK_BYTES), "r"(mbar_addr)
                : "memory");
        }
        // Wait phase c.
        {
            uint32_t done;
            asm volatile(
                "{\n\t"
                ".reg .pred p;\n\t"
                "mbarrier.try_wait.parity.acquire.cta.shared::cta.b64 p, [%1], %2;\n\t"
                "selp.b32 %0, 1, 0, p;\n\t"
                "}"
                : "=r"(done) : "r"(mbar_addr), "r"((uint32_t)c) : "memory");
            if (!done) {
                asm volatile(
                    "{\n\t"
                    ".reg .pred P1;\n\t"
                    "WL_%=:\n\t"
                    "mbarrier.try_wait.parity.acquire.cta.shared::cta.b64 P1, [%0], %1, 0x989680;\n\t"
                    "@P1 bra.uni WD_%=;\n\t"
                    "bra.uni WL_%=;\n\t"
                    "WD_%=:\n\t"
                    "}"
                    :: "r"(mbar_addr), "r"((uint32_t)c) : "memory");
            }
        }
        // Accumulate this 16KB chunk: 4096 floats / 256 threads = 4 float4 each.
        const float4* b4 = reinterpret_cast<const float4*>(buf);
        #pragma unroll
        for (int k = 0; k < 4; ++k) {
            float4 v = b4[threadIdx.x + k * THREADS];
            acc += (v.x + v.y) + (v.z + v.w);
        }
        __syncthreads();   // everyone done reading buf before next TMA overwrite
    }

    #pragma unroll
    for (int off = 16; off > 0; off >>= 1) {
        acc += __shfl_xor_sync(0xffffffffu, acc, off);
    }
    if (lid == 0) sh_a[wid] = acc;
    __syncthreads();

    if (threadIdx.x == 0) {
        float total = sh_a[0];
        #pragma unroll
        for (int w = 1; w < THREADS / 32; ++w) total += sh_a[w];
        out[0] = total * (1.0f / (float)B_ROWS);
    }
}

extern "C" void kernel_launch(void* const* d_in, const int* in_sizes, int n_in,
                              void* d_out, int out_size) {
    const float* inp = (const float*)d_in[0];
    const int* tgt = (const int*)d_in[1];
    float* out = (float*)d_out;

    ce_fused_kernel<<<B_ROWS + 1, THREADS>>>(inp, tgt, out);
}